// round 14
// baseline (speedup 1.0000x reference)
#include <cuda_runtime.h>
#include <cstdint>
#include <math.h>

// AttentionAggregator — final-form shape (R9) + lane-parallel index resolve
// and match_any dedup. 12 rounds established dur ≈ 0.25us/MB of gathered
// bytes regardless of path (LDG/cp.async/TMA/dual), i.e. an ~33-outstanding-
// line/SM concurrency wall; this round removes the remaining serial index
// and ALU overhead from the fastest measured variant.
// features: [100000, 256] f32; nodes: [4096] i32; unique_ids: [16384] i32;
// neigh_idx: [4096, 10] i32. out: [4096, 256] f32.

#define N_NODES 4096
#define FDIM    256
#define NSAMP   10
#define SM_ROW_F4 64
#define SM_WARP_F4 ((1 + NSAMP) * SM_ROW_F4)   // q_B + 10 embed rows

__device__ __forceinline__ void cp_async16(unsigned int dst, const void* src) {
    asm volatile("cp.async.cg.shared.global [%0], [%1], 16;"
                 :: "r"(dst), "l"(src));
}

__device__ __forceinline__ void stcs128(float* p, float4 v) {
    asm volatile("st.global.cs.v4.f32 [%0], {%1,%2,%3,%4};"
                 :: "l"(p), "f"(v.x), "f"(v.y), "f"(v.z), "f"(v.w));
}

__global__ __launch_bounds__(32)
void attn_agg_kernel(const float* __restrict__ feat,
                     const int*   __restrict__ nodes,
                     const int*   __restrict__ uids,
                     const int*   __restrict__ nidx,
                     float*       __restrict__ out)
{
    const int lane = threadIdx.x & 31;
    const int row0 = blockIdx.x * 2;              // A=row0, B=row0+1

    __shared__ float4 wbuf[SM_WARP_F4];
    const unsigned int sbase = (unsigned int)__cvta_generic_to_shared(wbuf);

    // --- lane-parallel index resolve: lanes 0..19 own one sample each.
    // One coalesced 80B nidx access + ONE gather instruction for all 20 uids.
    int col_l = 0, uid_l = 0;
    if (lane < 2 * NSAMP) {
        col_l = nidx[row0 * NSAMP + lane];
        uid_l = uids[col_l];
    }
    const int2 nn = *(const int2*)(nodes + row0);

    // --- row A FIRST: 22 independent LDG.128, addresses via shfl broadcast ---
    const float4* qpA = (const float4*)(feat + (size_t)nn.x * FDIM);
    const float4 qA0 = qpA[lane];
    const float4 qA1 = qpA[lane + 32];

    float4 a0[NSAMP], a1[NSAMP];
    #pragma unroll
    for (int s = 0; s < NSAMP; s++) {
        const int u = __shfl_sync(0xffffffffu, uid_l, s);
        const float4* ep = (const float4*)(feat + (size_t)u * FDIM);
        a0[s] = ep[lane];
        a1[s] = ep[lane + 32];
    }

    // --- then row B into SMEM: 22 cp.async per lane, zero regs held ---
    {
        const float* qB = feat + (size_t)nn.y * FDIM;
        cp_async16(sbase + (unsigned int)lane * 16u,        qB + lane * 4);
        cp_async16(sbase + (unsigned int)(lane + 32) * 16u, qB + (lane + 32) * 4);
        #pragma unroll
        for (int s = 0; s < NSAMP; s++) {
            const int u = __shfl_sync(0xffffffffu, uid_l, NSAMP + s);
            const float* eB = feat + (size_t)u * FDIM;
            const unsigned int off = sbase + (unsigned int)(1 + s) * 1024u;
            cp_async16(off + (unsigned int)lane * 16u,        eB + lane * 4);
            cp_async16(off + (unsigned int)(lane + 32) * 16u, eB + (lane + 32) * 4);
        }
        asm volatile("cp.async.commit_group;" ::: "memory");
    }

    // --- dedup via match_any while loads fly (mask counts repeated cols once).
    // Lanes 0-9 = row A samples, lanes 10-19 = row B samples.
    bool dupl = false;
    if (lane < NSAMP) {
        unsigned mm = __match_any_sync(0x000003FFu, col_l);
        dupl = (mm & ((1u << lane) - 1u)) != 0u;
    } else if (lane < 2 * NSAMP) {
        unsigned mm = __match_any_sync(0x000FFC00u, col_l);
        dupl = (mm & ((1u << lane) - 1u)) != 0u;
    }
    const unsigned db  = __ballot_sync(0xffffffffu, dupl);
    const unsigned dupA = db & 0x3FFu;
    const unsigned dupB = (db >> NSAMP) & 0x3FFu;

    // --- row A: dots + butterfly reduce ---
    float dots[NSAMP];
    #pragma unroll
    for (int s = 0; s < NSAMP; s++) {
        float a = a0[s].x*qA0.x + a0[s].y*qA0.y + a0[s].z*qA0.z + a0[s].w*qA0.w
                + a1[s].x*qA1.x + a1[s].y*qA1.y + a1[s].z*qA1.z + a1[s].w*qA1.w;
        #pragma unroll
        for (int o = 16; o; o >>= 1)
            a += __shfl_xor_sync(0xffffffffu, a, o);
        dots[s] = a;
    }

    // softmax A (redundant per lane) + aggregate + streaming store
    {
        float m = -INFINITY;
        #pragma unroll
        for (int s = 0; s < NSAMP; s++)
            if (!((dupA >> s) & 1u)) m = fmaxf(m, dots[s]);
        float sum = 0.f;
        #pragma unroll
        for (int s = 0; s < NSAMP; s++) {
            float e = ((dupA >> s) & 1u) ? 0.f : __expf(dots[s] - m);
            dots[s] = e; sum += e;
        }
        const float inv = 1.f / sum;

        float4 o0 = make_float4(0.f,0.f,0.f,0.f);
        float4 o1 = make_float4(0.f,0.f,0.f,0.f);
        #pragma unroll
        for (int s = 0; s < NSAMP; s++) {
            const float ws = dots[s] * inv;
            o0.x += ws*a0[s].x; o0.y += ws*a0[s].y;
            o0.z += ws*a0[s].z; o0.w += ws*a0[s].w;
            o1.x += ws*a1[s].x; o1.y += ws*a1[s].y;
            o1.z += ws*a1[s].z; o1.w += ws*a1[s].w;
        }
        float* op = out + (size_t)row0 * FDIM;
        stcs128(op + lane * 4, o0);
        stcs128(op + (lane + 32) * 4, o1);
    }

    // --- row B: compute from SMEM (each lane reads back its own copies) ---
    asm volatile("cp.async.wait_group 0;" ::: "memory");
    __syncwarp();

    const float4 qB0 = wbuf[lane];
    const float4 qB1 = wbuf[lane + 32];

    #pragma unroll
    for (int s = 0; s < NSAMP; s++) {
        const float4 b0 = wbuf[(1 + s) * SM_ROW_F4 + lane];
        const float4 b1 = wbuf[(1 + s) * SM_ROW_F4 + lane + 32];
        float a = b0.x*qB0.x + b0.y*qB0.y + b0.z*qB0.z + b0.w*qB0.w
                + b1.x*qB1.x + b1.y*qB1.y + b1.z*qB1.z + b1.w*qB1.w;
        #pragma unroll
        for (int o = 16; o; o >>= 1)
            a += __shfl_xor_sync(0xffffffffu, a, o);
        dots[s] = a;
    }

    {
        float m = -INFINITY;
        #pragma unroll
        for (int s = 0; s < NSAMP; s++)
            if (!((dupB >> s) & 1u)) m = fmaxf(m, dots[s]);
        float sum = 0.f;
        #pragma unroll
        for (int s = 0; s < NSAMP; s++) {
            float e = ((dupB >> s) & 1u) ? 0.f : __expf(dots[s] - m);
            dots[s] = e; sum += e;
        }
        const float inv = 1.f / sum;

        float4 o0 = make_float4(0.f,0.f,0.f,0.f);
        float4 o1 = make_float4(0.f,0.f,0.f,0.f);
        #pragma unroll
        for (int s = 0; s < NSAMP; s++) {
            const float ws = dots[s] * inv;
            const float4 b0 = wbuf[(1 + s) * SM_ROW_F4 + lane];
            const float4 b1 = wbuf[(1 + s) * SM_ROW_F4 + lane + 32];
            o0.x += ws*b0.x; o0.y += ws*b0.y;
            o0.z += ws*b0.z; o0.w += ws*b0.w;
            o1.x += ws*b1.x; o1.y += ws*b1.y;
            o1.z += ws*b1.z; o1.w += ws*b1.w;
        }
        float* op = out + (size_t)(row0 + 1) * FDIM;
        stcs128(op + lane * 4, o0);
        stcs128(op + (lane + 32) * 4, o1);
    }
}

extern "C" void kernel_launch(void* const* d_in, const int* in_sizes, int n_in,
                              void* d_out, int out_size)
{
    const float* feat  = (const float*)d_in[0];
    const int*   nodes = (const int*)  d_in[1];
    const int*   uids  = (const int*)  d_in[2];
    const int*   nidx  = (const int*)  d_in[3];
    float*       out   = (float*)d_out;
    (void)in_sizes; (void)n_in; (void)out_size;

    attn_agg_kernel<<<N_NODES / 2, 32>>>(feat, nodes, uids, nidx, out);
}

// round 15
// speedup vs baseline: 1.0240x; 1.0240x over previous
#include <cuda_runtime.h>
#include <cstdint>
#include <math.h>

// AttentionAggregator — R9 best-kernel-time shape + L2::evict_last pinning.
// 13 rounds: dur invariant (~10.3us kernel) across every issue-path shape =>
// fixed outstanding-line cap; throughput = lines*128B/latency. ncu shows
// ~18MB DRAM traffic PER REPLAY (= the unique-row working set), i.e. L2 is
// not retaining the hot rows between graph replays. This round pins every
// feature-row access with L2::evict_last (LDG cache_hint + cp.async
// cache_hint) to convert steady-state first-touch DRAM misses into L2 hits —
// the only term no prior round touched.
// features: [100000, 256] f32; nodes: [4096] i32; unique_ids: [16384] i32;
// neigh_idx: [4096, 10] i32. out: [4096, 256] f32.

#define N_NODES 4096
#define FDIM    256
#define NSAMP   10
#define SM_ROW_F4 64
#define SM_WARP_F4 ((1 + NSAMP) * SM_ROW_F4)   // q_B + 10 embed rows

__device__ __forceinline__ unsigned long long evict_last_policy() {
    unsigned long long pol;
    asm("createpolicy.fractional.L2::evict_last.b64 %0, 1.0;" : "=l"(pol));
    return pol;
}

__device__ __forceinline__ float4 ldg128_el(const float4* p,
                                            unsigned long long pol) {
    float4 v;
    asm volatile("ld.global.L2::cache_hint.v4.f32 {%0,%1,%2,%3}, [%4], %5;"
                 : "=f"(v.x), "=f"(v.y), "=f"(v.z), "=f"(v.w)
                 : "l"(p), "l"(pol));
    return v;
}

__device__ __forceinline__ void cp_async16_el(unsigned int dst, const void* src,
                                              unsigned long long pol) {
    asm volatile("cp.async.cg.shared.global.L2::cache_hint [%0], [%1], 16, %2;"
                 :: "r"(dst), "l"(src), "l"(pol));
}

__device__ __forceinline__ void stcs128(float* p, float4 v) {
    asm volatile("st.global.cs.v4.f32 [%0], {%1,%2,%3,%4};"
                 :: "l"(p), "f"(v.x), "f"(v.y), "f"(v.z), "f"(v.w));
}

__global__ __launch_bounds__(32)
void attn_agg_kernel(const float* __restrict__ feat,
                     const int*   __restrict__ nodes,
                     const int*   __restrict__ uids,
                     const int*   __restrict__ nidx,
                     float*       __restrict__ out)
{
    const int lane = threadIdx.x & 31;
    const int row0 = blockIdx.x * 2;              // A=row0, B=row0+1

    __shared__ float4 wbuf[SM_WARP_F4];
    const unsigned int sbase = (unsigned int)__cvta_generic_to_shared(wbuf);
    const unsigned long long pol = evict_last_policy();

    // --- indices for both rows, warp-uniform (80B contiguous -> 5x int4) ---
    int cols[2 * NSAMP];
    {
        const int4* np = (const int4*)(nidx + (size_t)row0 * NSAMP);
        #pragma unroll
        for (int i = 0; i < 5; i++) {
            int4 v = np[i];
            cols[4*i+0] = v.x; cols[4*i+1] = v.y;
            cols[4*i+2] = v.z; cols[4*i+3] = v.w;
        }
    }
    int uid[2 * NSAMP];
    #pragma unroll
    for (int s = 0; s < 2 * NSAMP; s++)
        uid[s] = uids[cols[s]];
    const int2 nn = *(const int2*)(nodes + row0);

    // --- row A FIRST: 22 independent LDG.128, L2 evict_last ---
    const float4* qpA = (const float4*)(feat + (size_t)nn.x * FDIM);
    const float4 qA0 = ldg128_el(qpA + lane, pol);
    const float4 qA1 = ldg128_el(qpA + lane + 32, pol);

    float4 a0[NSAMP], a1[NSAMP];
    #pragma unroll
    for (int s = 0; s < NSAMP; s++) {
        const float4* ep = (const float4*)(feat + (size_t)uid[s] * FDIM);
        a0[s] = ldg128_el(ep + lane, pol);
        a1[s] = ldg128_el(ep + lane + 32, pol);
    }

    // --- then row B into SMEM: 22 cp.async (evict_last), zero regs held ---
    {
        const float* qB = feat + (size_t)nn.y * FDIM;
        cp_async16_el(sbase + (unsigned int)lane * 16u,        qB + lane * 4, pol);
        cp_async16_el(sbase + (unsigned int)(lane + 32) * 16u, qB + (lane + 32) * 4, pol);
        #pragma unroll
        for (int s = 0; s < NSAMP; s++) {
            const float* eB = feat + (size_t)uid[NSAMP + s] * FDIM;
            const unsigned int off = sbase + (unsigned int)(1 + s) * 1024u;
            cp_async16_el(off + (unsigned int)lane * 16u,        eB + lane * 4, pol);
            cp_async16_el(off + (unsigned int)(lane + 32) * 16u, eB + (lane + 32) * 4, pol);
        }
        asm volatile("cp.async.commit_group;" ::: "memory");
    }

    // --- dup masks while loads fly (dense mask counts repeated cols once) ---
    unsigned dup[2] = {0u, 0u};
    #pragma unroll
    for (int r = 0; r < 2; r++)
        #pragma unroll
        for (int s = 1; s < NSAMP; s++) {
            bool d = false;
            #pragma unroll
            for (int t = 0; t < NSAMP; t++)
                if (t < s) d |= (cols[r*NSAMP+t] == cols[r*NSAMP+s]);
            if (d) dup[r] |= (1u << s);
        }

    // --- row A: dots + butterfly reduce ---
    float dots[NSAMP];
    #pragma unroll
    for (int s = 0; s < NSAMP; s++) {
        float a = a0[s].x*qA0.x + a0[s].y*qA0.y + a0[s].z*qA0.z + a0[s].w*qA0.w
                + a1[s].x*qA1.x + a1[s].y*qA1.y + a1[s].z*qA1.z + a1[s].w*qA1.w;
        #pragma unroll
        for (int o = 16; o; o >>= 1)
            a += __shfl_xor_sync(0xffffffffu, a, o);
        dots[s] = a;
    }

    // softmax A (redundant per lane) + aggregate + streaming store
    {
        float m = -INFINITY;
        #pragma unroll
        for (int s = 0; s < NSAMP; s++)
            if (!((dup[0] >> s) & 1u)) m = fmaxf(m, dots[s]);
        float sum = 0.f;
        #pragma unroll
        for (int s = 0; s < NSAMP; s++) {
            float e = ((dup[0] >> s) & 1u) ? 0.f : __expf(dots[s] - m);
            dots[s] = e; sum += e;
        }
        const float inv = 1.f / sum;

        float4 o0 = make_float4(0.f,0.f,0.f,0.f);
        float4 o1 = make_float4(0.f,0.f,0.f,0.f);
        #pragma unroll
        for (int s = 0; s < NSAMP; s++) {
            const float ws = dots[s] * inv;
            o0.x += ws*a0[s].x; o0.y += ws*a0[s].y;
            o0.z += ws*a0[s].z; o0.w += ws*a0[s].w;
            o1.x += ws*a1[s].x; o1.y += ws*a1[s].y;
            o1.z += ws*a1[s].z; o1.w += ws*a1[s].w;
        }
        float* op = out + (size_t)row0 * FDIM;
        stcs128(op + lane * 4, o0);
        stcs128(op + (lane + 32) * 4, o1);
    }

    // --- row B: compute from SMEM (each lane reads back its own copies) ---
    asm volatile("cp.async.wait_group 0;" ::: "memory");
    __syncwarp();

    const float4 qB0 = wbuf[lane];
    const float4 qB1 = wbuf[lane + 32];

    #pragma unroll
    for (int s = 0; s < NSAMP; s++) {
        const float4 b0 = wbuf[(1 + s) * SM_ROW_F4 + lane];
        const float4 b1 = wbuf[(1 + s) * SM_ROW_F4 + lane + 32];
        float a = b0.x*qB0.x + b0.y*qB0.y + b0.z*qB0.z + b0.w*qB0.w
                + b1.x*qB1.x + b1.y*qB1.y + b1.z*qB1.z + b1.w*qB1.w;
        #pragma unroll
        for (int o = 16; o; o >>= 1)
            a += __shfl_xor_sync(0xffffffffu, a, o);
        dots[s] = a;
    }

    {
        float m = -INFINITY;
        #pragma unroll
        for (int s = 0; s < NSAMP; s++)
            if (!((dup[1] >> s) & 1u)) m = fmaxf(m, dots[s]);
        float sum = 0.f;
        #pragma unroll
        for (int s = 0; s < NSAMP; s++) {
            float e = ((dup[1] >> s) & 1u) ? 0.f : __expf(dots[s] - m);
            dots[s] = e; sum += e;
        }
        const float inv = 1.f / sum;

        float4 o0 = make_float4(0.f,0.f,0.f,0.f);
        float4 o1 = make_float4(0.f,0.f,0.f,0.f);
        #pragma unroll
        for (int s = 0; s < NSAMP; s++) {
            const float ws = dots[s] * inv;
            const float4 b0 = wbuf[(1 + s) * SM_ROW_F4 + lane];
            const float4 b1 = wbuf[(1 + s) * SM_ROW_F4 + lane + 32];
            o0.x += ws*b0.x; o0.y += ws*b0.y;
            o0.z += ws*b0.z; o0.w += ws*b0.w;
            o1.x += ws*b1.x; o1.y += ws*b1.y;
            o1.z += ws*b1.z; o1.w += ws*b1.w;
        }
        float* op = out + (size_t)(row0 + 1) * FDIM;
        stcs128(op + lane * 4, o0);
        stcs128(op + (lane + 32) * 4, o1);
    }
}

extern "C" void kernel_launch(void* const* d_in, const int* in_sizes, int n_in,
                              void* d_out, int out_size)
{
    const float* feat  = (const float*)d_in[0];
    const int*   nodes = (const int*)  d_in[1];
    const int*   uids  = (const int*)  d_in[2];
    const int*   nidx  = (const int*)  d_in[3];
    float*       out   = (float*)d_out;
    (void)in_sizes; (void)n_in; (void)out_size;

    attn_agg_kernel<<<N_NODES / 2, 32>>>(feat, nodes, uids, nidx, out);
}